// round 16
// baseline (speedup 1.0000x reference)
#include <cuda_runtime.h>
#include <cuda_bf16.h>
#include <cstdint>

#define N_ROWS 32768
#define K_EMB  8192
#define D_DIM  512
#define Q_ELEMS (N_ROWS * D_DIM)   // 16,777,216
#define CAND_CAP 128
#define MARGIN 1.25e-4f

// ---------------- scratch (static device memory; no allocations) -----------
__device__ float         g_a[N_ROWS];
__device__ int           g_idx[N_ROWS];
__device__ int           g_correct;
__device__ __nv_bfloat16 g_eh[K_EMB * D_DIM];         //  8 MB
__device__ int           g_cand[N_ROWS * CAND_CAP];   // 16 MB
__device__ float         g_csc[N_ROWS * CAND_CAP];    // 16 MB
__device__ int           g_cnt[N_ROWS];
__device__ float         g_gmax[N_ROWS];

// ---------------- baseline PTX helpers (no 'a'-gated features) -------------
__device__ __forceinline__ uint32_t smem_u32(const void* p) {
    uint32_t a;
    asm("{ .reg .u64 t; cvta.to.shared.u64 t, %1; cvt.u32.u64 %0, t; }"
        : "=r"(a) : "l"(p));
    return a;
}
#define LDSM_X4(R, addr)                                                     \
    asm volatile("ldmatrix.sync.aligned.m8n8.x4.shared.b16 {%0,%1,%2,%3}, [%4];" \
        : "=r"((R)[0]), "=r"((R)[1]), "=r"((R)[2]), "=r"((R)[3]) : "r"(addr))
__device__ __forceinline__ void mma_bf16(float* c, const uint32_t* a,
                                         const uint32_t* b) {
    asm volatile(
        "mma.sync.aligned.m16n8k16.row.col.f32.bf16.bf16.f32 "
        "{%0,%1,%2,%3}, {%4,%5,%6,%7}, {%8,%9}, {%0,%1,%2,%3};"
        : "+f"(c[0]), "+f"(c[1]), "+f"(c[2]), "+f"(c[3])
        : "r"(a[0]), "r"(a[1]), "r"(a[2]), "r"(a[3]), "r"(b[0]), "r"(b[1]));
}
#define CP_ASYNC16(dst, src)                                                 \
    asm volatile("cp.async.cg.shared.global [%0], [%1], 16;" :: "r"(dst), "l"(src))
#define CP_COMMIT()  asm volatile("cp.async.commit_group;" ::: "memory")
#define CP_WAIT_ALL() asm volatile("cp.async.wait_group 0;" ::: "memory")
#define SWZ(off) ((off) ^ (((off) >> 3) & 0x70))

__device__ __forceinline__ uint32_t pack_bf16x2(float a, float b) {
    __nv_bfloat162 h = __float22bfloat162_rn(make_float2(a, b));
    return *(uint32_t*)&h;
}

// ---------------- emb convert (f32 -> bf16) + init -------------------------
// One warp per emb row; block 0 thread 0 also zeroes g_correct.
__global__ __launch_bounds__(256)
void vq_embconv_kernel(const float* __restrict__ emb) {
    if (blockIdx.x == 0 && threadIdx.x == 0) g_correct = 0;
    const int wid = threadIdx.x >> 5, lid = threadIdx.x & 31;
    const int row = blockIdx.x * 8 + wid;
    const float4* src = (const float4*)(emb + (size_t)row * D_DIM) + lid * 4;
    uint32_t w[8];
#pragma unroll
    for (int t = 0; t < 4; ++t) {
        float4 v = __ldg(src + t);
        w[t * 2 + 0] = pack_bf16x2(v.x, v.y);
        w[t * 2 + 1] = pack_bf16x2(v.z, v.w);
    }
    uint4* dst = (uint4*)(g_eh + (size_t)row * D_DIM + lid * 16);
    dst[0] = make_uint4(w[0], w[1], w[2], w[3]);
    dst[1] = make_uint4(w[4], w[5], w[6], w[7]);
}

// ---------------- HMMA GEMM + shortlist (R6 config + fused A prologue) -----
// CTA: 128 rows x all codes. A loaded DIRECTLY from f32 latents in the
// prologue: fp64 row norms (bit-identical order to the old convnorm) ->
// g_a, bf16 conversion in registers -> resident swizzled smem tile. The
// 32MB g_xh round-trip and the whole latents pre-pass disappear.
// B streamed 32KB chunks (256 codes x 64 k), cp.async double buffer.
// 16 warps: 4(m) x 4(n); warp tile 32 x 64; m16n8k16 bf16 HMMA.
#define SMA_BYTES (8 * 16384)                  // 131072
#define SMB_OFF   SMA_BYTES
#define CHUNK_B   32768                        // 256 codes x 64 k x 2B
#define SCNT_OFF  (SMB_OFF + 2 * CHUNK_B)      // 196608
#define SWMAX_OFF (SCNT_OFF + 512)             // 197120
#define SMEM_TOTAL (SWMAX_OFF + 128 * 4 * 4)   // 199168
#define NITER 256                              // 32 n-tiles x 8 k-chunks

__global__ __launch_bounds__(512, 1)
void vq_gemm_kernel(const float* __restrict__ lat) {
    extern __shared__ __align__(1024) char smem[];
    const uint32_t sb = smem_u32(smem);
    const int tid = threadIdx.x, wid = tid >> 5, lane = tid & 31;
    const int wm = wid >> 2, wn = wid & 3;     // 4m x 4n
    const int r0 = blockIdx.x * 128;
    int* scnt = (int*)(smem + SCNT_OFF);
    float* swmax = (float*)(smem + SWMAX_OFF);

    if (tid < 128) scnt[tid] = 0;

    // fused A prologue: warp w handles rows w*8 .. w*8+7.
    // Per row: lane reads float4s [lane*4 .. lane*4+3] (elems [lane*16,+16)),
    // fp64 norm in the exact old convnorm order, bf16-pack, store swizzled.
    {
        char* cb = smem + (lane >> 2) * 16384;
        const uint32_t rb = (lane & 3) * 32;
#pragma unroll 1
        for (int rr = 0; rr < 8; ++rr) {
            const int row = wid * 8 + rr;
            const float4* src =
                (const float4*)(lat + (size_t)(r0 + row) * D_DIM) + lane * 4;
            uint32_t w[8];
            double s = 0.0;
#pragma unroll
            for (int t = 0; t < 4; ++t) {
                float4 v = __ldg(src + t);
                w[t * 2 + 0] = pack_bf16x2(v.x, v.y);
                w[t * 2 + 1] = pack_bf16x2(v.z, v.w);
                s += (double)v.x * v.x + (double)v.y * v.y +
                     (double)v.z * v.z + (double)v.w * v.w;
            }
            *(uint4*)(cb + SWZ(row * 128 + rb)) =
                make_uint4(w[0], w[1], w[2], w[3]);
            *(uint4*)(cb + SWZ(row * 128 + rb + 16)) =
                make_uint4(w[4], w[5], w[6], w[7]);
#pragma unroll
            for (int o = 16; o; o >>= 1)
                s += __shfl_down_sync(0xffffffffu, s, o);
            if (lane == 0) g_a[r0 + row] = (float)s;
        }
    }

    // B chunk loader (cp.async, 32KB): idx = ntile*8 + kc
    auto load_chunk = [&](int idx, int buf) {
        const int nt = idx >> 3, kc = idx & 7;
        const __nv_bfloat16* base = g_eh + (size_t)(nt * 256) * D_DIM + kc * 64;
        const uint32_t dsb = sb + SMB_OFF + buf * CHUNK_B;
#pragma unroll
        for (int j = 0; j < 4; ++j) {
            int g2 = tid + j * 512;
            int rr = g2 >> 3, g16 = g2 & 7;
            CP_ASYNC16(dsb + SWZ(rr * 128 + g16 * 16),
                       base + (size_t)rr * D_DIM + g16 * 8);
        }
        CP_COMMIT();
    };

    load_chunk(0, 0);

    // per-thread invariant ldmatrix address pieces (non-trans layouts)
    const int rowA = wm * 32 + (lane & 15);                          // + mt*16
    const int kbA  = (lane >> 4) * 16;                               // + s*32
    const int rowB = wn * 64 + ((lane >> 4) & 1) * 8 + (lane & 7);   // + p*16
    const int kbB  = ((lane >> 3) & 1) * 16;                         // + s*32

    float acc[2][8][4];
#pragma unroll
    for (int mt = 0; mt < 2; ++mt)
#pragma unroll
        for (int nt = 0; nt < 8; ++nt)
#pragma unroll
            for (int j = 0; j < 4; ++j) acc[mt][nt][j] = 0.0f;

    float rm[4];
#pragma unroll
    for (int j = 0; j < 4; ++j) rm[j] = -3.4e38f;

    for (int idx = 0; idx < NITER; ++idx) {
        CP_WAIT_ALL();        // chunk idx resident (issued one iter earlier)
        __syncthreads();      // A tile + chunk visible; warps done with idx-1
        if (idx + 1 < NITER) load_chunk(idx + 1, (idx + 1) & 1);

        const uint32_t sbA = sb + (idx & 7) * 16384;
        const uint32_t sbB = sb + SMB_OFF + (idx & 1) * CHUNK_B;
#pragma unroll
        for (int s = 0; s < 4; ++s) {
            uint32_t afr[2][4];
#pragma unroll
            for (int mt = 0; mt < 2; ++mt)
                LDSM_X4(afr[mt], sbA + SWZ((rowA + mt * 16) * 128 + s * 32 + kbA));
            uint32_t bfr[4][4];
#pragma unroll
            for (int p = 0; p < 4; ++p)
                LDSM_X4(bfr[p], sbB + SWZ((rowB + p * 16) * 128 + s * 32 + kbB));
#pragma unroll
            for (int mt = 0; mt < 2; ++mt)
#pragma unroll
                for (int nt = 0; nt < 8; ++nt)
                    mma_bf16(acc[mt][nt], afr[mt], &bfr[nt >> 1][(nt & 1) * 2]);
        }

        if ((idx & 7) == 7) {
            // ---- epilogue for finished 256-wide N-tile ----
            const int ntile = idx >> 3;
#pragma unroll
            for (int mt = 0; mt < 2; ++mt) {
                float v0 = -3.4e38f, v1 = -3.4e38f;
#pragma unroll
                for (int nt = 0; nt < 8; ++nt) {
                    v0 = fmaxf(v0, fmaxf(acc[mt][nt][0], acc[mt][nt][1]));
                    v1 = fmaxf(v1, fmaxf(acc[mt][nt][2], acc[mt][nt][3]));
                }
                v0 = fmaxf(v0, __shfl_xor_sync(0xffffffffu, v0, 1));
                v0 = fmaxf(v0, __shfl_xor_sync(0xffffffffu, v0, 2));
                v1 = fmaxf(v1, __shfl_xor_sync(0xffffffffu, v1, 1));
                v1 = fmaxf(v1, __shfl_xor_sync(0xffffffffu, v1, 2));
                rm[mt * 2]     = fmaxf(rm[mt * 2], v0);
                rm[mt * 2 + 1] = fmaxf(rm[mt * 2 + 1], v1);
                const float thr0 = rm[mt * 2] - MARGIN;
                const float thr1 = rm[mt * 2 + 1] - MARGIN;
                const int rl0 = wm * 32 + mt * 16 + (lane >> 2);
#pragma unroll
                for (int nt = 0; nt < 8; ++nt) {
#pragma unroll
                    for (int j = 0; j < 4; ++j) {
                        const float sc = acc[mt][nt][j];
                        const float th = (j < 2) ? thr0 : thr1;
                        if (sc >= th) {
                            const int rl = rl0 + ((j >> 1) * 8);
                            const int code = ntile * 256 + wn * 64 +
                                             (nt >> 1) * 16 + (nt & 1) * 8 +
                                             (lane & 3) * 2 + (j & 1);
                            int pos = atomicAdd(&scnt[rl], 1);
                            if (pos < CAND_CAP) {
                                g_cand[(size_t)(r0 + rl) * CAND_CAP + pos] = code;
                                g_csc[(size_t)(r0 + rl) * CAND_CAP + pos] = sc;
                            }
                        }
                        acc[mt][nt][j] = 0.0f;
                    }
                }
            }
        }
    }

    // per-warp maxes -> smem -> global
    __syncthreads();
    if ((lane & 3) == 0) {
#pragma unroll
        for (int mt = 0; mt < 2; ++mt) {
            int rl = wm * 32 + mt * 16 + (lane >> 2);
            swmax[rl * 4 + wn] = rm[mt * 2];
            swmax[(rl + 8) * 4 + wn] = rm[mt * 2 + 1];
        }
    }
    __syncthreads();
    if (tid < 128) {
        float g = fmaxf(fmaxf(swmax[tid * 4 + 0], swmax[tid * 4 + 1]),
                        fmaxf(swmax[tid * 4 + 2], swmax[tid * 4 + 3]));
        g_gmax[r0 + tid] = g;
        g_cnt[r0 + tid] = scnt[tid];
    }
}

// ---------------- fused exact rescore + outputs (R10 version — best) -------
__global__ __launch_bounds__(256)
void vq_rescore_out_kernel(const float* __restrict__ lat,
                           const float* __restrict__ emb,
                           const int* __restrict__ gold,
                           float* __restrict__ out, int full) {
    __shared__ float xs[8][D_DIM];
    const int wid = threadIdx.x >> 5, lid = threadIdx.x & 31;
    const int row = blockIdx.x * 8 + wid;
    {
        float4* d = (float4*)xs[wid];
        const float4* s = (const float4*)(lat + (size_t)row * D_DIM);
#pragma unroll
        for (int j = 0; j < 4; ++j) d[lid + j * 32] = s[lid + j * 32];
    }
    __syncwarp();
    const int cnt = g_cnt[row];
    const float a = g_a[row];
    const float thr = g_gmax[row] - MARGIN;
    float dist = 3.4e38f;
    int kk = 0x7fffffff;
    const float* x = xs[wid];
    if (cnt <= CAND_CAP) {
        for (int c = lid; c < cnt; c += 32) {
            if (g_csc[(size_t)row * CAND_CAP + c] < thr) continue;
            const int k = g_cand[(size_t)row * CAND_CAP + c];
            const float4* e4 = (const float4*)(emb + (size_t)k * D_DIM);
            float acc = 0.0f;
#pragma unroll 8
            for (int d4 = 0; d4 < D_DIM / 4; ++d4) {
                float4 ev = __ldg(e4 + d4);
                acc = fmaf(x[d4 * 4 + 0], ev.x, acc);
                acc = fmaf(x[d4 * 4 + 1], ev.y, acc);
                acc = fmaf(x[d4 * 4 + 2], ev.z, acc);
                acc = fmaf(x[d4 * 4 + 3], ev.w, acc);
            }
            float dd = __fmaf_rn(-2.0f, acc, a);
            if (dd < dist || (dd == dist && k < kk)) { dist = dd; kk = k; }
        }
    } else {
        // overflow fallback: exact scan of all codes (statistically never)
        for (int kb = 0; kb < K_EMB; kb += 32) {
            const int k = kb + lid;
            const float4* e4 = (const float4*)(emb + (size_t)k * D_DIM);
            float acc = 0.0f;
            for (int d4 = 0; d4 < D_DIM / 4; ++d4) {
                float4 ev = __ldg(e4 + d4);
                acc = fmaf(x[d4 * 4 + 0], ev.x, acc);
                acc = fmaf(x[d4 * 4 + 1], ev.y, acc);
                acc = fmaf(x[d4 * 4 + 2], ev.z, acc);
                acc = fmaf(x[d4 * 4 + 3], ev.w, acc);
            }
            float dd = __fmaf_rn(-2.0f, acc, a);
            if (dd < dist || (dd == dist && k < kk)) { dist = dd; kk = k; }
        }
    }
#pragma unroll
    for (int off = 16; off; off >>= 1) {
        float od = __shfl_down_sync(0xffffffffu, dist, off);
        int ok = __shfl_down_sync(0xffffffffu, kk, off);
        if (od < dist || (od == dist && ok < kk)) { dist = od; kk = ok; }
    }
    kk = __shfl_sync(0xffffffffu, kk, 0);

    // outputs: quantized = fl(x + fl(q-x)), loss, index, correct
    const float4* q4 = (const float4*)(emb + (size_t)kk * D_DIM);
    float4* o4 = (float4*)(out + (size_t)row * D_DIM);
    const float4* x4 = (const float4*)xs[wid];
    float ss = 0.0f;
#pragma unroll
    for (int j = 0; j < 4; ++j) {
        const int i = lid + j * 32;
        float4 xv = x4[i];
        float4 qv = __ldg(q4 + i);
        float4 dv, ov;
        dv.x = qv.x - xv.x; dv.y = qv.y - xv.y;
        dv.z = qv.z - xv.z; dv.w = qv.w - xv.w;
        ov.x = xv.x + dv.x; ov.y = xv.y + dv.y;
        ov.z = xv.z + dv.z; ov.w = xv.w + dv.w;
        o4[i] = ov;
        ss += dv.x * dv.x + dv.y * dv.y + dv.z * dv.z + dv.w * dv.w;
    }
#pragma unroll
    for (int off = 16; off; off >>= 1) ss += __shfl_down_sync(0xffffffffu, ss, off);
    if (lid == 0) {
        g_idx[row] = kk;
        if (gold[row] == kk) atomicAdd(&g_correct, 1);
        if (full) {
            float ml = ss * (1.0f / 512.0f);
            out[Q_ELEMS + row] = ml + 0.25f * ml;
            out[Q_ELEMS + N_ROWS + row] = (float)kk;
        }
    }
}

__global__ void vq_finalize_kernel(float* __restrict__ out, int full) {
    if (full) {
        out[Q_ELEMS + 2 * N_ROWS + 0] = (float)g_correct;
        out[Q_ELEMS + 2 * N_ROWS + 1] = (float)N_ROWS;
    }
}

// ---------------------------------------------------------------------------
extern "C" void kernel_launch(void* const* d_in, const int* in_sizes, int n_in,
                              void* d_out, int out_size) {
    const int* gold = nullptr;
    const float* lat = nullptr;
    const float* emb = nullptr;
    for (int i = 0; i < n_in; ++i) {
        if (in_sizes[i] == N_ROWS) gold = (const int*)d_in[i];
        else if (in_sizes[i] == Q_ELEMS) lat = (const float*)d_in[i];
        else if (in_sizes[i] == K_EMB * D_DIM) emb = (const float*)d_in[i];
    }
    float* out = (float*)d_out;
    int full = (out_size >= Q_ELEMS + 2 * N_ROWS + 2) ? 1 : 0;

    cudaFuncSetAttribute(vq_gemm_kernel,
                         cudaFuncAttributeMaxDynamicSharedMemorySize,
                         SMEM_TOTAL);

    vq_embconv_kernel<<<K_EMB / 8, 256>>>(emb);
    vq_gemm_kernel<<<N_ROWS / 128, 512, SMEM_TOTAL>>>(lat);
    vq_rescore_out_kernel<<<N_ROWS / 8, 256>>>(lat, emb, gold, out, full);
    vq_finalize_kernel<<<1, 1>>>(out, full);
}

// round 17
// speedup vs baseline: 1.0330x; 1.0330x over previous
#include <cuda_runtime.h>
#include <cuda_bf16.h>
#include <cstdint>

#define N_ROWS 32768
#define K_EMB  8192
#define D_DIM  512
#define Q_ELEMS (N_ROWS * D_DIM)   // 16,777,216
#define CAND_CAP 128
#define MARGIN 1.25e-4f

// ---------------- scratch (static device memory; no allocations) -----------
__device__ float         g_a[N_ROWS];
__device__ int           g_idx[N_ROWS];
__device__ int           g_correct;
__device__ int           g_done;
__device__ __nv_bfloat16 g_xh[N_ROWS * D_DIM];        // 32 MB
__device__ __nv_bfloat16 g_eh[K_EMB * D_DIM];         //  8 MB
__device__ int           g_cand[N_ROWS * CAND_CAP];   // 16 MB
__device__ float         g_csc[N_ROWS * CAND_CAP];    // 16 MB
__device__ int           g_cnt[N_ROWS];
__device__ float         g_gmax[N_ROWS];

// ---------------- baseline PTX helpers (no 'a'-gated features) -------------
__device__ __forceinline__ uint32_t smem_u32(const void* p) {
    uint32_t a;
    asm("{ .reg .u64 t; cvta.to.shared.u64 t, %1; cvt.u32.u64 %0, t; }"
        : "=r"(a) : "l"(p));
    return a;
}
#define LDSM_X4(R, addr)                                                     \
    asm volatile("ldmatrix.sync.aligned.m8n8.x4.shared.b16 {%0,%1,%2,%3}, [%4];" \
        : "=r"((R)[0]), "=r"((R)[1]), "=r"((R)[2]), "=r"((R)[3]) : "r"(addr))
__device__ __forceinline__ void mma_bf16(float* c, const uint32_t* a,
                                         const uint32_t* b) {
    asm volatile(
        "mma.sync.aligned.m16n8k16.row.col.f32.bf16.bf16.f32 "
        "{%0,%1,%2,%3}, {%4,%5,%6,%7}, {%8,%9}, {%0,%1,%2,%3};"
        : "+f"(c[0]), "+f"(c[1]), "+f"(c[2]), "+f"(c[3])
        : "r"(a[0]), "r"(a[1]), "r"(a[2]), "r"(a[3]), "r"(b[0]), "r"(b[1]));
}
#define CP_ASYNC16(dst, src)                                                 \
    asm volatile("cp.async.cg.shared.global [%0], [%1], 16;" :: "r"(dst), "l"(src))
#define CP_COMMIT()  asm volatile("cp.async.commit_group;" ::: "memory")
#define CP_WAIT_ALL() asm volatile("cp.async.wait_group 0;" ::: "memory")
#define SWZ(off) ((off) ^ (((off) >> 3) & 0x70))

__device__ __forceinline__ uint32_t pack_bf16x2(float a, float b) {
    __nv_bfloat162 h = __float22bfloat162_rn(make_float2(a, b));
    return *(uint32_t*)&h;
}

// ---------------- fused convert (f32 -> bf16) + fp64 row norms + init ------
// One warp per row. blocks [0,4096): latents (+ norms); [4096,5120): emb.
__global__ __launch_bounds__(256)
void vq_convnorm_kernel(const float* __restrict__ lat,
                        const float* __restrict__ emb) {
    if (blockIdx.x == 0 && threadIdx.x == 0) { g_correct = 0; g_done = 0; }
    const int wid = threadIdx.x >> 5, lid = threadIdx.x & 31;
    const int b = blockIdx.x;
    if (b < 4096) {
        const int row = b * 8 + wid;
        const float4* src = (const float4*)(lat + (size_t)row * D_DIM) + lid * 4;
        uint32_t w[8];
        double s = 0.0;
#pragma unroll
        for (int t = 0; t < 4; ++t) {
            float4 v = __ldg(src + t);
            w[t * 2 + 0] = pack_bf16x2(v.x, v.y);
            w[t * 2 + 1] = pack_bf16x2(v.z, v.w);
            s += (double)v.x * v.x + (double)v.y * v.y +
                 (double)v.z * v.z + (double)v.w * v.w;
        }
        uint4* dst = (uint4*)(g_xh + (size_t)row * D_DIM + lid * 16);
        dst[0] = make_uint4(w[0], w[1], w[2], w[3]);
        dst[1] = make_uint4(w[4], w[5], w[6], w[7]);
#pragma unroll
        for (int o = 16; o; o >>= 1) s += __shfl_down_sync(0xffffffffu, s, o);
        if (lid == 0) g_a[row] = (float)s;
    } else {
        const int row = (b - 4096) * 8 + wid;
        const float4* src = (const float4*)(emb + (size_t)row * D_DIM) + lid * 4;
        uint32_t w[8];
#pragma unroll
        for (int t = 0; t < 4; ++t) {
            float4 v = __ldg(src + t);
            w[t * 2 + 0] = pack_bf16x2(v.x, v.y);
            w[t * 2 + 1] = pack_bf16x2(v.z, v.w);
        }
        uint4* dst = (uint4*)(g_eh + (size_t)row * D_DIM + lid * 16);
        dst[0] = make_uint4(w[0], w[1], w[2], w[3]);
        dst[1] = make_uint4(w[4], w[5], w[6], w[7]);
    }
}

// ---------------- HMMA GEMM + shortlist (R6 config — best measured) --------
// CTA: 128 rows x all codes. A resident (8 chunks of 128x64 bf16, SW128),
// loaded via cp.async (raw bf16 copy). B streamed 32KB chunks, double buffer.
// 16 warps: 4(m) x 4(n); warp tile 32 x 64; m16n8k16 bf16 HMMA.
#define SMA_BYTES (8 * 16384)                  // 131072
#define SMB_OFF   SMA_BYTES
#define CHUNK_B   32768                        // 256 codes x 64 k x 2B
#define SCNT_OFF  (SMB_OFF + 2 * CHUNK_B)      // 196608
#define SWMAX_OFF (SCNT_OFF + 512)             // 197120
#define SMEM_TOTAL (SWMAX_OFF + 128 * 4 * 4)   // 199168
#define NITER 256                              // 32 n-tiles x 8 k-chunks

__global__ __launch_bounds__(512, 1)
void vq_gemm_kernel() {
    extern __shared__ __align__(1024) char smem[];
    const uint32_t sb = smem_u32(smem);
    const int tid = threadIdx.x, wid = tid >> 5, lane = tid & 31;
    const int wm = wid >> 2, wn = wid & 3;     // 4m x 4n
    const int r0 = blockIdx.x * 128;
    int* scnt = (int*)(smem + SCNT_OFF);
    float* swmax = (float*)(smem + SWMAX_OFF);

    if (tid < 128) scnt[tid] = 0;

    // resident A via cp.async: 128 rows x 512 k bf16, swizzled, 8x16KB chunks
    for (int g = tid; g < 8192; g += 512) {
        int r = g >> 6, w = g & 63, kc = w >> 3, gg = w & 7;
        CP_ASYNC16(sb + kc * 16384 + SWZ(r * 128 + gg * 16),
                   g_xh + (size_t)(r0 + r) * D_DIM + kc * 64 + gg * 8);
    }
    CP_COMMIT();

    // B chunk loader (cp.async, 32KB): idx = ntile*8 + kc
    auto load_chunk = [&](int idx, int buf) {
        const int nt = idx >> 3, kc = idx & 7;
        const __nv_bfloat16* base = g_eh + (size_t)(nt * 256) * D_DIM + kc * 64;
        const uint32_t dsb = sb + SMB_OFF + buf * CHUNK_B;
#pragma unroll
        for (int j = 0; j < 4; ++j) {
            int g2 = tid + j * 512;
            int rr = g2 >> 3, g16 = g2 & 7;
            CP_ASYNC16(dsb + SWZ(rr * 128 + g16 * 16),
                       base + (size_t)rr * D_DIM + g16 * 8);
        }
        CP_COMMIT();
    };

    load_chunk(0, 0);

    // per-thread invariant ldmatrix address pieces (non-trans layouts)
    const int rowA = wm * 32 + (lane & 15);                          // + mt*16
    const int kbA  = (lane >> 4) * 16;                               // + s*32
    const int rowB = wn * 64 + ((lane >> 4) & 1) * 8 + (lane & 7);   // + p*16
    const int kbB  = ((lane >> 3) & 1) * 16;                         // + s*32

    float acc[2][8][4];
#pragma unroll
    for (int mt = 0; mt < 2; ++mt)
#pragma unroll
        for (int nt = 0; nt < 8; ++nt)
#pragma unroll
            for (int j = 0; j < 4; ++j) acc[mt][nt][j] = 0.0f;

    float rm[4];
#pragma unroll
    for (int j = 0; j < 4; ++j) rm[j] = -3.4e38f;

    for (int idx = 0; idx < NITER; ++idx) {
        CP_WAIT_ALL();        // A tile (iter 0) + chunk idx resident
        __syncthreads();      // visible to all; all warps done with idx-1
        if (idx + 1 < NITER) load_chunk(idx + 1, (idx + 1) & 1);

        const uint32_t sbA = sb + (idx & 7) * 16384;
        const uint32_t sbB = sb + SMB_OFF + (idx & 1) * CHUNK_B;
#pragma unroll
        for (int s = 0; s < 4; ++s) {
            uint32_t afr[2][4];
#pragma unroll
            for (int mt = 0; mt < 2; ++mt)
                LDSM_X4(afr[mt], sbA + SWZ((rowA + mt * 16) * 128 + s * 32 + kbA));
            uint32_t bfr[4][4];
#pragma unroll
            for (int p = 0; p < 4; ++p)
                LDSM_X4(bfr[p], sbB + SWZ((rowB + p * 16) * 128 + s * 32 + kbB));
#pragma unroll
            for (int mt = 0; mt < 2; ++mt)
#pragma unroll
                for (int nt = 0; nt < 8; ++nt)
                    mma_bf16(acc[mt][nt], afr[mt], &bfr[nt >> 1][(nt & 1) * 2]);
        }

        if ((idx & 7) == 7) {
            // ---- epilogue for finished 256-wide N-tile ----
            const int ntile = idx >> 3;
#pragma unroll
            for (int mt = 0; mt < 2; ++mt) {
                float v0 = -3.4e38f, v1 = -3.4e38f;
#pragma unroll
                for (int nt = 0; nt < 8; ++nt) {
                    v0 = fmaxf(v0, fmaxf(acc[mt][nt][0], acc[mt][nt][1]));
                    v1 = fmaxf(v1, fmaxf(acc[mt][nt][2], acc[mt][nt][3]));
                }
                v0 = fmaxf(v0, __shfl_xor_sync(0xffffffffu, v0, 1));
                v0 = fmaxf(v0, __shfl_xor_sync(0xffffffffu, v0, 2));
                v1 = fmaxf(v1, __shfl_xor_sync(0xffffffffu, v1, 1));
                v1 = fmaxf(v1, __shfl_xor_sync(0xffffffffu, v1, 2));
                rm[mt * 2]     = fmaxf(rm[mt * 2], v0);
                rm[mt * 2 + 1] = fmaxf(rm[mt * 2 + 1], v1);
                const float thr0 = rm[mt * 2] - MARGIN;
                const float thr1 = rm[mt * 2 + 1] - MARGIN;
                const int rl0 = wm * 32 + mt * 16 + (lane >> 2);
#pragma unroll
                for (int nt = 0; nt < 8; ++nt) {
#pragma unroll
                    for (int j = 0; j < 4; ++j) {
                        const float sc = acc[mt][nt][j];
                        const float th = (j < 2) ? thr0 : thr1;
                        if (sc >= th) {
                            const int rl = rl0 + ((j >> 1) * 8);
                            const int code = ntile * 256 + wn * 64 +
                                             (nt >> 1) * 16 + (nt & 1) * 8 +
                                             (lane & 3) * 2 + (j & 1);
                            int pos = atomicAdd(&scnt[rl], 1);
                            if (pos < CAND_CAP) {
                                g_cand[(size_t)(r0 + rl) * CAND_CAP + pos] = code;
                                g_csc[(size_t)(r0 + rl) * CAND_CAP + pos] = sc;
                            }
                        }
                        acc[mt][nt][j] = 0.0f;
                    }
                }
            }
        }
    }

    // per-warp maxes -> smem -> global
    __syncthreads();
    if ((lane & 3) == 0) {
#pragma unroll
        for (int mt = 0; mt < 2; ++mt) {
            int rl = wm * 32 + mt * 16 + (lane >> 2);
            swmax[rl * 4 + wn] = rm[mt * 2];
            swmax[(rl + 8) * 4 + wn] = rm[mt * 2 + 1];
        }
    }
    __syncthreads();
    if (tid < 128) {
        float g = fmaxf(fmaxf(swmax[tid * 4 + 0], swmax[tid * 4 + 1]),
                        fmaxf(swmax[tid * 4 + 2], swmax[tid * 4 + 3]));
        g_gmax[r0 + tid] = g;
        g_cnt[r0 + tid] = scnt[tid];
    }
}

// ---------------- fused exact rescore + outputs + finalize -----------------
__global__ __launch_bounds__(256)
void vq_rescore_out_kernel(const float* __restrict__ lat,
                           const float* __restrict__ emb,
                           const int* __restrict__ gold,
                           float* __restrict__ out, int full) {
    __shared__ float xs[8][D_DIM];
    const int wid = threadIdx.x >> 5, lid = threadIdx.x & 31;
    const int row = blockIdx.x * 8 + wid;
    {
        float4* d = (float4*)xs[wid];
        const float4* s = (const float4*)(lat + (size_t)row * D_DIM);
#pragma unroll
        for (int j = 0; j < 4; ++j) d[lid + j * 32] = s[lid + j * 32];
    }
    __syncwarp();
    const int cnt = g_cnt[row];
    const float a = g_a[row];
    const float thr = g_gmax[row] - MARGIN;
    float dist = 3.4e38f;
    int kk = 0x7fffffff;
    const float* x = xs[wid];
    if (cnt <= CAND_CAP) {
        for (int c = lid; c < cnt; c += 32) {
            if (g_csc[(size_t)row * CAND_CAP + c] < thr) continue;
            const int k = g_cand[(size_t)row * CAND_CAP + c];
            const float4* e4 = (const float4*)(emb + (size_t)k * D_DIM);
            float acc = 0.0f;
#pragma unroll 8
            for (int d4 = 0; d4 < D_DIM / 4; ++d4) {
                float4 ev = __ldg(e4 + d4);
                acc = fmaf(x[d4 * 4 + 0], ev.x, acc);
                acc = fmaf(x[d4 * 4 + 1], ev.y, acc);
                acc = fmaf(x[d4 * 4 + 2], ev.z, acc);
                acc = fmaf(x[d4 * 4 + 3], ev.w, acc);
            }
            float dd = __fmaf_rn(-2.0f, acc, a);
            if (dd < dist || (dd == dist && k < kk)) { dist = dd; kk = k; }
        }
    } else {
        // overflow fallback: exact scan of all codes (statistically never)
        for (int kb = 0; kb < K_EMB; kb += 32) {
            const int k = kb + lid;
            const float4* e4 = (const float4*)(emb + (size_t)k * D_DIM);
            float acc = 0.0f;
            for (int d4 = 0; d4 < D_DIM / 4; ++d4) {
                float4 ev = __ldg(e4 + d4);
                acc = fmaf(x[d4 * 4 + 0], ev.x, acc);
                acc = fmaf(x[d4 * 4 + 1], ev.y, acc);
                acc = fmaf(x[d4 * 4 + 2], ev.z, acc);
                acc = fmaf(x[d4 * 4 + 3], ev.w, acc);
            }
            float dd = __fmaf_rn(-2.0f, acc, a);
            if (dd < dist || (dd == dist && k < kk)) { dist = dd; kk = k; }
        }
    }
#pragma unroll
    for (int off = 16; off; off >>= 1) {
        float od = __shfl_down_sync(0xffffffffu, dist, off);
        int ok = __shfl_down_sync(0xffffffffu, kk, off);
        if (od < dist || (od == dist && ok < kk)) { dist = od; kk = ok; }
    }
    kk = __shfl_sync(0xffffffffu, kk, 0);

    // outputs: quantized = fl(x + fl(q-x)), loss, index, correct
    const float4* q4 = (const float4*)(emb + (size_t)kk * D_DIM);
    float4* o4 = (float4*)(out + (size_t)row * D_DIM);
    const float4* x4 = (const float4*)xs[wid];
    float ss = 0.0f;
#pragma unroll
    for (int j = 0; j < 4; ++j) {
        const int i = lid + j * 32;
        float4 xv = x4[i];
        float4 qv = __ldg(q4 + i);
        float4 dv, ov;
        dv.x = qv.x - xv.x; dv.y = qv.y - xv.y;
        dv.z = qv.z - xv.z; dv.w = qv.w - xv.w;
        ov.x = xv.x + dv.x; ov.y = xv.y + dv.y;
        ov.z = xv.z + dv.z; ov.w = xv.w + dv.w;
        o4[i] = ov;
        ss += dv.x * dv.x + dv.y * dv.y + dv.z * dv.z + dv.w * dv.w;
    }
#pragma unroll
    for (int off = 16; off; off >>= 1) ss += __shfl_down_sync(0xffffffffu, ss, off);
    if (lid == 0) {
        g_idx[row] = kk;
        if (gold[row] == kk) atomicAdd(&g_correct, 1);
        if (full) {
            float ml = ss * (1.0f / 512.0f);
            out[Q_ELEMS + row] = ml + 0.25f * ml;
            out[Q_ELEMS + N_ROWS + row] = (float)kk;
        }
    }

    // finalize: last block to complete writes (correct, total)
    __syncthreads();
    if (threadIdx.x == 0) {
        __threadfence();
        int done = atomicAdd(&g_done, 1);
        if (done == gridDim.x - 1 && full) {
            out[Q_ELEMS + 2 * N_ROWS + 0] = (float)atomicAdd(&g_correct, 0);
            out[Q_ELEMS + 2 * N_ROWS + 1] = (float)N_ROWS;
        }
    }
}

// ---------------------------------------------------------------------------
extern "C" void kernel_launch(void* const* d_in, const int* in_sizes, int n_in,
                              void* d_out, int out_size) {
    const int* gold = nullptr;
    const float* lat = nullptr;
    const float* emb = nullptr;
    for (int i = 0; i < n_in; ++i) {
        if (in_sizes[i] == N_ROWS) gold = (const int*)d_in[i];
        else if (in_sizes[i] == Q_ELEMS) lat = (const float*)d_in[i];
        else if (in_sizes[i] == K_EMB * D_DIM) emb = (const float*)d_in[i];
    }
    float* out = (float*)d_out;
    int full = (out_size >= Q_ELEMS + 2 * N_ROWS + 2) ? 1 : 0;

    cudaFuncSetAttribute(vq_gemm_kernel,
                         cudaFuncAttributeMaxDynamicSharedMemorySize,
                         SMEM_TOTAL);

    vq_convnorm_kernel<<<4096 + 1024, 256>>>(lat, emb);
    vq_gemm_kernel<<<N_ROWS / 128, 512, SMEM_TOTAL>>>();
    vq_rescore_out_kernel<<<N_ROWS / 8, 256>>>(lat, emb, gold, out, full);
}